// round 1
// baseline (speedup 1.0000x reference)
#include <cuda_runtime.h>
#include <math.h>

#define NN   65536
#define BB   1024
#define EE   2097152
#define EEG  524288
#define DIM  128

// ---------------- static scratch (no runtime allocation allowed) ------------
__device__ float d_h   [(size_t)NN * DIM];   // node features
__device__ float d_bufA[(size_t)NN * DIM];   // move-edge aggregate / 'a' / lg
__device__ float d_bufG[(size_t)NN * DIM];   // grid-edge aggregate / 'g'
__device__ float d_v0[BB * DIM];
__device__ float d_v1[BB * DIM];

__device__ int d_csrM[EE];
__device__ int d_csrG[EEG];
__device__ int d_offM[NN + 1];
__device__ int d_offG[NN + 1];
__device__ int d_curM[NN];
__device__ int d_curG[NN];
__device__ int d_cntOutM[NN], d_cntInM[NN], d_cntOutG[NN], d_cntInG[NN];
__device__ float d_s1[NN], d_r1[NN], d_c1[NN];
__device__ float d_s2[NN], d_r2[NN], d_c2[NN];

// ---------------- degree / CSR precompute -----------------------------------
__global__ void k_zero_counts() {
    int i = blockIdx.x * blockDim.x + threadIdx.x;
    if (i < NN) { d_cntOutM[i] = 0; d_cntInM[i] = 0; d_cntOutG[i] = 0; d_cntInG[i] = 0; }
}

__global__ void k_hist(const int* __restrict__ snd, const int* __restrict__ rcv,
                       int ne, int* outc, int* inc) {
    int e = blockIdx.x * blockDim.x + threadIdx.x;
    if (e < ne) { atomicAdd(&outc[snd[e]], 1); atomicAdd(&inc[rcv[e]], 1); }
}

__global__ void k_norms() {
    int i = blockIdx.x * blockDim.x + threadIdx.x;
    if (i < NN) {
        // +1 for the self edge; degree therefore >= 1, max(.,1) is a no-op
        d_s1[i] = rsqrtf((float)(d_cntOutM[i] + 1));
        d_r1[i] = rsqrtf((float)(d_cntInM[i]  + 1));
        d_s2[i] = rsqrtf((float)(d_cntOutG[i] + 1));
        d_r2[i] = rsqrtf((float)(d_cntInG[i]  + 1));
    }
}

// single-block exclusive scan over NN=65536 counts (1024 threads x 64 items)
__global__ void k_scan(const int* __restrict__ cnt, int* __restrict__ off,
                       int* __restrict__ cur) {
    __shared__ int ps[1024];
    int t = threadIdx.x;
    int base = t * 64;
    int s = 0;
    for (int j = 0; j < 64; j++) s += cnt[base + j];
    ps[t] = s;
    __syncthreads();
    for (int d = 1; d < 1024; d <<= 1) {
        int v = 0;
        if (t >= d) v = ps[t - d];
        __syncthreads();
        ps[t] += v;
        __syncthreads();
    }
    int run = (t == 0) ? 0 : ps[t - 1];
    for (int j = 0; j < 64; j++) {
        off[base + j] = run;
        cur[base + j] = run;
        run += cnt[base + j];
    }
    if (t == 1023) off[NN] = run;
}

__global__ void k_scatter(const int* __restrict__ snd, const int* __restrict__ rcv,
                          int ne, int* cur, int* __restrict__ csr) {
    int e = blockIdx.x * blockDim.x + threadIdx.x;
    if (e < ne) {
        int p = atomicAdd(&cur[rcv[e]], 1);
        csr[p] = snd[e];
    }
}

// c[r] = s[r] + sum_{in-edges} s[snd]   (layer-invariant bias weight)
__global__ void k_csum(const int* __restrict__ off, const int* __restrict__ csr,
                       const float* __restrict__ sn, float* __restrict__ csum) {
    int i = blockIdx.x * blockDim.x + threadIdx.x;
    if (i < NN) {
        float c = sn[i];
        int e1 = off[i + 1];
        for (int e = off[i]; e < e1; e++) c += sn[csr[e]];
        csum[i] = c;
    }
}

// ---------------- embedding --------------------------------------------------
__global__ void k_embed(const int* __restrict__ nodes, const float* __restrict__ embed,
                        float* __restrict__ h) {
    int i = blockIdx.x * blockDim.x + threadIdx.x;   // over NN*32 float4s
    if (i < NN * 32) {
        int node = i >> 5;
        int c    = i & 31;
        ((float4*)h)[i] = ((const float4*)embed)[nodes[node] * 32 + c];
    }
}

// ---------------- pull-based aggregation (no atomics) ------------------------
// out[r,:] = s[r]*h[r,:] + sum_{e in CSR[r]} s[snd]*h[snd,:]
__global__ void k_agg(const float* __restrict__ h, const int* __restrict__ off,
                      const int* __restrict__ csr, const float* __restrict__ sn,
                      float* __restrict__ out) {
    int gw   = (blockIdx.x * blockDim.x + threadIdx.x) >> 5;  // one warp per node
    int lane = threadIdx.x & 31;
    if (gw >= NN) return;
    const float4* h4 = (const float4*)h;
    float s0 = sn[gw];
    float4 a = h4[(size_t)gw * 32 + lane];
    float4 acc;
    acc.x = a.x * s0; acc.y = a.y * s0; acc.z = a.z * s0; acc.w = a.w * s0;
    int e1 = off[gw + 1];
    for (int e = off[gw]; e < e1; e++) {
        int   s  = csr[e];
        float sc = sn[s];
        float4 v = h4[(size_t)s * 32 + lane];
        acc.x = fmaf(v.x, sc, acc.x);
        acc.y = fmaf(v.y, sc, acc.y);
        acc.z = fmaf(v.z, sc, acc.z);
        acc.w = fmaf(v.w, sc, acc.w);
    }
    ((float4*)out)[(size_t)gw * 32 + lane] = acc;
}

// ---------------- fused GEMM: C = rrow * (A @ W + bias * crow), opt relu -----
// A is [n,K] built from Alo (k<128) and Ahi (k>=128), each row-major [n,128].
// BM=64, BN=128, BK=16, 256 threads, 8x4 outputs per thread.
__global__ void __launch_bounds__(256)
k_gemm(const float* Alo, const float* Ahi,
       const float* __restrict__ W, const float* __restrict__ bias,
       const float* __restrict__ crow, const float* __restrict__ rrow,
       float* C, int K, int relu) {
    __shared__ float As[16][64];
    __shared__ float Ws[16][128];
    int tid = threadIdx.x;
    int rowBase = blockIdx.x * 64;
    int row0 = (tid >> 5) * 8;
    int col0 = (tid & 31) * 4;
    int lr = tid >> 2, lk = (tid & 3) * 4;
    int wr = tid >> 4, wc = (tid & 15) * 8;

    float acc[8][4];
#pragma unroll
    for (int i = 0; i < 8; i++)
#pragma unroll
        for (int j = 0; j < 4; j++) acc[i][j] = 0.f;

    for (int kt = 0; kt < K; kt += 16) {
        const float* src = (kt < 128) ? Alo : Ahi;
        int kk = (kt < 128) ? kt : (kt - 128);
        float4 a4 = *(const float4*)&src[(size_t)(rowBase + lr) * 128 + kk + lk];
        As[lk + 0][lr] = a4.x;
        As[lk + 1][lr] = a4.y;
        As[lk + 2][lr] = a4.z;
        As[lk + 3][lr] = a4.w;
        float4 w0 = *(const float4*)&W[(size_t)(kt + wr) * 128 + wc];
        float4 w1 = *(const float4*)&W[(size_t)(kt + wr) * 128 + wc + 4];
        *(float4*)&Ws[wr][wc]     = w0;
        *(float4*)&Ws[wr][wc + 4] = w1;
        __syncthreads();
#pragma unroll
        for (int k = 0; k < 16; k++) {
            float4 wv = *(const float4*)&Ws[k][col0];
            float4 aA = *(const float4*)&As[k][row0];
            float4 aB = *(const float4*)&As[k][row0 + 4];
            float av[8] = {aA.x, aA.y, aA.z, aA.w, aB.x, aB.y, aB.z, aB.w};
            float wf[4] = {wv.x, wv.y, wv.z, wv.w};
#pragma unroll
            for (int i = 0; i < 8; i++)
#pragma unroll
                for (int j = 0; j < 4; j++)
                    acc[i][j] = fmaf(av[i], wf[j], acc[i][j]);
        }
        __syncthreads();
    }

    float4 bv = *(const float4*)&bias[col0];
#pragma unroll
    for (int i = 0; i < 8; i++) {
        int row = rowBase + row0 + i;
        float cm = crow ? crow[row] : 1.f;
        float rm = rrow ? rrow[row] : 1.f;
        float4 o;
        o.x = (acc[i][0] + bv.x * cm) * rm;
        o.y = (acc[i][1] + bv.y * cm) * rm;
        o.z = (acc[i][2] + bv.z * cm) * rm;
        o.w = (acc[i][3] + bv.w * cm) * rm;
        if (relu) {
            o.x = fmaxf(o.x, 0.f); o.y = fmaxf(o.y, 0.f);
            o.z = fmaxf(o.z, 0.f); o.w = fmaxf(o.w, 0.f);
        }
        *(float4*)&C[(size_t)row * 128 + col0] = o;
    }
}

// ---------------- edge logits: dot(lg[s], lg[r]) -----------------------------
__global__ void k_edge_logits(const float* __restrict__ lg, const int* __restrict__ snd,
                              const int* __restrict__ rcv, float* __restrict__ out) {
    int gw   = (blockIdx.x * blockDim.x + threadIdx.x) >> 5;   // warp per edge
    int lane = threadIdx.x & 31;
    if (gw >= EE) return;
    const float4* l4 = (const float4*)lg;
    int s = snd[gw], r = rcv[gw];
    float4 a = l4[(size_t)s * 32 + lane];
    float4 b = l4[(size_t)r * 32 + lane];
    float p = a.x * b.x + a.y * b.y + a.z * b.z + a.w * b.w;
#pragma unroll
    for (int o = 16; o > 0; o >>= 1) p += __shfl_down_sync(0xffffffffu, p, o);
    if (lane == 0) out[gw] = p;
}

// ---------------- value head -------------------------------------------------
__global__ void k_value_reduce(const float* __restrict__ h, float* __restrict__ v) {
    int g = blockIdx.x, t = threadIdx.x;   // 128 threads, one block per graph
    float acc = 0.f;
    for (int j = 1; j < 64; j++)           // mask excludes local node 0
        acc += h[((size_t)(g * 64 + j)) * 128 + t];
    v[g * 128 + t] = acc * (1.f / 63.f);
}

__global__ void k_tanh_out(const float* __restrict__ v, const float* __restrict__ wout,
                           const float* __restrict__ bout, float* __restrict__ out) {
    int gw   = (blockIdx.x * blockDim.x + threadIdx.x) >> 5;
    int lane = threadIdx.x & 31;
    if (gw >= BB) return;
    const float4* v4 = (const float4*)v;
    const float4* w4 = (const float4*)wout;
    float4 a = v4[gw * 32 + lane];
    float4 w = w4[lane];
    float p = a.x * w.x + a.y * w.y + a.z * w.z + a.w * w.w;
#pragma unroll
    for (int o = 16; o > 0; o >>= 1) p += __shfl_down_sync(0xffffffffu, p, o);
    if (lane == 0) out[gw] = tanhf(p + bout[0]);
}

// ---------------- host launcher ----------------------------------------------
extern "C" void kernel_launch(void* const* d_in, const int* in_sizes, int n_in,
                              void* d_out, int out_size) {
    const int*   nodes = (const int*)d_in[0];
    const int*   snd   = (const int*)d_in[1];
    const int*   rcv   = (const int*)d_in[2];
    const int*   gsnd  = (const int*)d_in[3];
    const int*   grcv  = (const int*)d_in[4];
    const float* embed = (const float*)d_in[6];
    const float* w1    = (const float*)d_in[7];
    const float* b1    = (const float*)d_in[8];
    const float* w2    = (const float*)d_in[9];
    const float* b2    = (const float*)d_in[10];
    const float* w3    = (const float*)d_in[11];
    const float* b3    = (const float*)d_in[12];
    const float* wl    = (const float*)d_in[13];
    const float* bl    = (const float*)d_in[14];
    const float* ew    = (const float*)d_in[15];
    const float* eb    = (const float*)d_in[16];
    const float* wo    = (const float*)d_in[17];
    const float* bo    = (const float*)d_in[18];
    float* out = (float*)d_out;

    float *h, *bufA, *bufG, *v0, *v1, *s1, *r1, *c1, *s2, *r2, *c2;
    int *csrM, *csrG, *offM, *offG, *curM, *curG, *cInM, *cInG, *cOutM, *cOutG;
    cudaGetSymbolAddress((void**)&h,    d_h);
    cudaGetSymbolAddress((void**)&bufA, d_bufA);
    cudaGetSymbolAddress((void**)&bufG, d_bufG);
    cudaGetSymbolAddress((void**)&v0,   d_v0);
    cudaGetSymbolAddress((void**)&v1,   d_v1);
    cudaGetSymbolAddress((void**)&s1,   d_s1);
    cudaGetSymbolAddress((void**)&r1,   d_r1);
    cudaGetSymbolAddress((void**)&c1,   d_c1);
    cudaGetSymbolAddress((void**)&s2,   d_s2);
    cudaGetSymbolAddress((void**)&r2,   d_r2);
    cudaGetSymbolAddress((void**)&c2,   d_c2);
    cudaGetSymbolAddress((void**)&csrM, d_csrM);
    cudaGetSymbolAddress((void**)&csrG, d_csrG);
    cudaGetSymbolAddress((void**)&offM, d_offM);
    cudaGetSymbolAddress((void**)&offG, d_offG);
    cudaGetSymbolAddress((void**)&curM, d_curM);
    cudaGetSymbolAddress((void**)&curG, d_curG);
    cudaGetSymbolAddress((void**)&cInM, d_cntInM);
    cudaGetSymbolAddress((void**)&cInG, d_cntInG);
    cudaGetSymbolAddress((void**)&cOutM, d_cntOutM);
    cudaGetSymbolAddress((void**)&cOutG, d_cntOutG);

    // ---- degree / CSR precompute (layer-invariant) ----
    k_zero_counts<<<NN / 256, 256>>>();
    k_hist<<<(EE  + 255) / 256, 256>>>(snd,  rcv,  EE,  cOutM, cInM);
    k_hist<<<(EEG + 255) / 256, 256>>>(gsnd, grcv, EEG, cOutG, cInG);
    k_norms<<<NN / 256, 256>>>();
    k_scan<<<1, 1024>>>(cInM, offM, curM);
    k_scan<<<1, 1024>>>(cInG, offG, curG);
    k_scatter<<<(EE  + 255) / 256, 256>>>(snd,  rcv,  EE,  curM, csrM);
    k_scatter<<<(EEG + 255) / 256, 256>>>(gsnd, grcv, EEG, curG, csrG);
    k_csum<<<NN / 256, 256>>>(offM, csrM, s1, c1);
    k_csum<<<NN / 256, 256>>>(offG, csrG, s2, c2);

    // ---- embed ----
    k_embed<<<(NN * 32 + 255) / 256, 256>>>(nodes, embed, h);

    // ---- 7 GNN layers ----
    for (int i = 0; i < 7; i++) {
        k_agg<<<NN * 32 / 256, 256>>>(h, offM, csrM, s1, bufA);
        k_agg<<<NN * 32 / 256, 256>>>(h, offG, csrG, s2, bufG);
        k_gemm<<<NN / 64, 256>>>(bufA, nullptr, w1 + (size_t)i * 128 * 128,
                                 b1 + i * 128, c1, r1, bufA, 128, 0);
        k_gemm<<<NN / 64, 256>>>(bufG, nullptr, w2 + (size_t)i * 128 * 128,
                                 b2 + i * 128, c2, r2, bufG, 128, 0);
        k_gemm<<<NN / 64, 256>>>(bufA, bufG, w3 + (size_t)i * 256 * 128,
                                 b3 + i * 128, nullptr, nullptr, h, 256, 1);
    }

    // ---- policy head: lg = h @ w_logit + b_logit; logits = dot(lg[s], lg[r]) ----
    k_gemm<<<NN / 64, 256>>>(h, nullptr, wl, bl, nullptr, nullptr, bufA, 128, 0);
    k_edge_logits<<<(EE * 32) / 256, 256>>>(bufA, snd, rcv, out);

    // ---- value head ----
    k_value_reduce<<<BB, 128>>>(h, v0);
    const float* vin = v0;
    float* vout = v1;
    for (int i = 0; i < 5; i++) {
        k_gemm<<<BB / 64, 256>>>(vin, nullptr, ew + (size_t)i * 128 * 128,
                                 eb + i * 128, nullptr, nullptr, vout, 128, 1);
        const float* t = vin; vin = vout; vout = (float*)t;
    }
    k_tanh_out<<<BB * 32 / 256, 256>>>(vin, wo, bo, out + EE);
}

// round 4
// speedup vs baseline: 1.2437x; 1.2437x over previous
#include <cuda_runtime.h>
#include <cuda_bf16.h>
#include <math.h>
#include <stdint.h>

#define NN   65536
#define BB   1024
#define EE   2097152
#define EEG  524288
#define DIM  128

// ======================= portable PTX helpers ================================
__device__ __forceinline__ uint32_t smem_to_u32(const void* p) {
    uint32_t a;
    asm("{ .reg .u64 t; cvta.to.shared.u64 t, %1; cvt.u32.u64 %0, t; }" : "=r"(a) : "l"(p));
    return a;
}

__device__ __forceinline__ void ldsm4(uint32_t* r, uint32_t addr) {
    asm volatile("ldmatrix.sync.aligned.m8n8.x4.shared.b16 {%0,%1,%2,%3}, [%4];"
                 : "=r"(r[0]), "=r"(r[1]), "=r"(r[2]), "=r"(r[3]) : "r"(addr));
}

__device__ __forceinline__ void mma16816(float* c, const uint32_t* a, const uint32_t* b) {
    asm volatile("mma.sync.aligned.m16n8k16.row.col.f32.bf16.bf16.f32 "
                 "{%0,%1,%2,%3}, {%4,%5,%6,%7}, {%8,%9}, {%0,%1,%2,%3};"
                 : "+f"(c[0]), "+f"(c[1]), "+f"(c[2]), "+f"(c[3])
                 : "r"(a[0]), "r"(a[1]), "r"(a[2]), "r"(a[3]), "r"(b[0]), "r"(b[1]));
}

// ======================= static scratch ======================================
__device__ float d_h   [(size_t)NN * DIM];   // node features (fp32)
__device__ float d_lg  [(size_t)NN * DIM];   // logit-head features (fp32)
__device__ float d_v0[BB * DIM];
__device__ float d_v1[BB * DIM];

__device__ __nv_bfloat16 d_mHi[(size_t)NN * DIM], d_mLo[(size_t)NN * DIM];
__device__ __nv_bfloat16 d_gHi[(size_t)NN * DIM], d_gLo[(size_t)NN * DIM];

// converted transposed weights (bf16 hi/lo), layout [n][K]
__device__ __nv_bfloat16 d_wt1h[7*128*128], d_wt1l[7*128*128];
__device__ __nv_bfloat16 d_wt2h[7*128*128], d_wt2l[7*128*128];
__device__ __nv_bfloat16 d_wt3h[7*128*256], d_wt3l[7*128*256];
__device__ __nv_bfloat16 d_wtlh[128*128],   d_wtll[128*128];

__device__ int d_csrM[EE];
__device__ int d_csrG[EEG];
__device__ int d_offM[NN + 1];
__device__ int d_offG[NN + 1];
__device__ int d_curM[NN];
__device__ int d_curG[NN];
__device__ int d_cntOutM[NN], d_cntInM[NN], d_cntOutG[NN], d_cntInG[NN];
__device__ float d_s1[NN], d_r1[NN], d_c1[NN];
__device__ float d_s2[NN], d_r2[NN], d_c2[NN];

// ======================= degree / CSR precompute =============================
__global__ void k_zero_counts() {
    int i = blockIdx.x * blockDim.x + threadIdx.x;
    if (i < NN) { d_cntOutM[i] = 0; d_cntInM[i] = 0; d_cntOutG[i] = 0; d_cntInG[i] = 0; }
}

__global__ void k_hist(const int* __restrict__ snd, const int* __restrict__ rcv,
                       int ne, int* outc, int* inc) {
    int e = blockIdx.x * blockDim.x + threadIdx.x;
    if (e < ne) { atomicAdd(&outc[snd[e]], 1); atomicAdd(&inc[rcv[e]], 1); }
}

__global__ void k_norms() {
    int i = blockIdx.x * blockDim.x + threadIdx.x;
    if (i < NN) {
        d_s1[i] = rsqrtf((float)(d_cntOutM[i] + 1));
        d_r1[i] = rsqrtf((float)(d_cntInM[i]  + 1));
        d_s2[i] = rsqrtf((float)(d_cntOutG[i] + 1));
        d_r2[i] = rsqrtf((float)(d_cntInG[i]  + 1));
    }
}

__global__ void k_scan(const int* __restrict__ cnt, int* __restrict__ off,
                       int* __restrict__ cur) {
    __shared__ int ps[1024];
    int t = threadIdx.x;
    int base = t * 64;
    int s = 0;
    for (int j = 0; j < 64; j++) s += cnt[base + j];
    ps[t] = s;
    __syncthreads();
    for (int d = 1; d < 1024; d <<= 1) {
        int v = 0;
        if (t >= d) v = ps[t - d];
        __syncthreads();
        ps[t] += v;
        __syncthreads();
    }
    int run = (t == 0) ? 0 : ps[t - 1];
    for (int j = 0; j < 64; j++) {
        off[base + j] = run;
        cur[base + j] = run;
        run += cnt[base + j];
    }
    if (t == 1023) off[NN] = run;
}

__global__ void k_scatter(const int* __restrict__ snd, const int* __restrict__ rcv,
                          int ne, int* cur, int* __restrict__ csr) {
    int e = blockIdx.x * blockDim.x + threadIdx.x;
    if (e < ne) {
        int p = atomicAdd(&cur[rcv[e]], 1);
        csr[p] = snd[e];
    }
}

__global__ void k_csum(const int* __restrict__ off, const int* __restrict__ csr,
                       const float* __restrict__ sn, float* __restrict__ csum) {
    int i = blockIdx.x * blockDim.x + threadIdx.x;
    if (i < NN) {
        float c = sn[i];
        int e1 = off[i + 1];
        for (int e = off[i]; e < e1; e++) c += sn[csr[e]];
        csum[i] = c;
    }
}

// ======================= weight convert (transpose + hi/lo bf16) =============
// W: [K][128] fp32 -> out[n*K + k] = split(W[k][n])
__global__ void k_wt(const float* __restrict__ W, __nv_bfloat16* __restrict__ hi,
                     __nv_bfloat16* __restrict__ lo, int K) {
    int id = blockIdx.x * blockDim.x + threadIdx.x;
    if (id >= K * 128) return;
    int n = id / K, k = id - n * K;
    float w = W[k * 128 + n];
    __nv_bfloat16 h = __float2bfloat16(w);
    hi[id] = h;
    lo[id] = __float2bfloat16(w - __bfloat162float(h));
}

// ======================= embedding ==========================================
__global__ void k_embed(const int* __restrict__ nodes, const float* __restrict__ embed,
                        float* __restrict__ h) {
    int i = blockIdx.x * blockDim.x + threadIdx.x;
    if (i < NN * 32) {
        int node = i >> 5;
        int c    = i & 31;
        ((float4*)h)[i] = ((const float4*)embed)[nodes[node] * 32 + c];
    }
}

// ======================= pull aggregation -> bf16 hi/lo pair =================
__global__ void k_aggP(const float* __restrict__ h, const int* __restrict__ off,
                       const int* __restrict__ csr, const float* __restrict__ sn,
                       __nv_bfloat16* __restrict__ oHi, __nv_bfloat16* __restrict__ oLo) {
    int gw   = (blockIdx.x * blockDim.x + threadIdx.x) >> 5;  // one warp per node
    int lane = threadIdx.x & 31;
    if (gw >= NN) return;
    const float4* h4 = (const float4*)h;
    float s0 = sn[gw];
    float4 a = h4[(size_t)gw * 32 + lane];
    float4 acc;
    acc.x = a.x * s0; acc.y = a.y * s0; acc.z = a.z * s0; acc.w = a.w * s0;
    int e1 = off[gw + 1];
    for (int e = off[gw]; e < e1; e++) {
        int   s  = csr[e];
        float sc = sn[s];
        float4 v = h4[(size_t)s * 32 + lane];
        acc.x = fmaf(v.x, sc, acc.x);
        acc.y = fmaf(v.y, sc, acc.y);
        acc.z = fmaf(v.z, sc, acc.z);
        acc.w = fmaf(v.w, sc, acc.w);
    }
    __nv_bfloat16 hv[4], lv[4];
    float av[4] = {acc.x, acc.y, acc.z, acc.w};
#pragma unroll
    for (int j = 0; j < 4; j++) {
        hv[j] = __float2bfloat16(av[j]);
        lv[j] = __float2bfloat16(av[j] - __bfloat162float(hv[j]));
    }
    size_t p = (size_t)gw * 128 + lane * 4;
    *(uint2*)&oHi[p] = *(uint2*)hv;
    *(uint2*)&oLo[p] = *(uint2*)lv;
}

// ======================= HMMA GEMM (mma.sync bf16, 3-pass compensated) =======
// C[row, 0:128] = rrow * ( sum_chunks A_chunk @ Wt_chunk^T + bias * crow ), opt relu
// A given as bf16 hi/lo pairs per 128-wide chunk (chunk0 = aHi/aLo, chunk1 = gHi/gLo).
// Wt layout: [n (0..127)][K], K = 128 * nchunks.
// smem tiles: 128 rows x 64 bf16, 128B pitch, xor-swizzled: off = r*128 + (cb ^ ((r&7)<<4))
#define SM_AH 0
#define SM_AL 16384
#define SM_WH 32768
#define SM_WL 49152
#define SM_TOTAL 65536

__global__ void __launch_bounds__(256)
k_mma(const __nv_bfloat16* __restrict__ aHi, const __nv_bfloat16* __restrict__ aLo,
      const __nv_bfloat16* __restrict__ gHi, const __nv_bfloat16* __restrict__ gLo,
      const __nv_bfloat16* __restrict__ wtHi, const __nv_bfloat16* __restrict__ wtLo,
      int K, const float* __restrict__ bias,
      const float* __restrict__ crow, const float* __restrict__ rrow,
      int relu, float* __restrict__ outF,
      __nv_bfloat16* __restrict__ outHi, __nv_bfloat16* __restrict__ outLo) {
    extern __shared__ __align__(16) char smem[];
    uint32_t sb = smem_to_u32(smem);
    int tid = threadIdx.x;
    int wid = tid >> 5;
    int l   = tid & 31;
    int rowBase = blockIdx.x * 128;
    int m0 = (wid >> 1) * 32;        // warp M offset (4 warps)
    int n0 = (wid & 1) * 64;         // warp N offset (2 warps)

    // per-lane ldmatrix address components
    int ra_base = m0 + (l & 7) + ((l >> 3) & 1) * 8;   // A row for x4 matrices
    uint32_t kxA = ((l >> 4) & 1) * 16;                // A k-byte offset (hi 16 lanes)
    uint32_t xorA = (uint32_t)((ra_base & 7) << 4);
    int rb_base = n0 + (l & 7) + ((l >> 4) & 1) * 8;   // B(n) row
    uint32_t kxB = ((l >> 3) & 1) * 16;
    uint32_t xorB = (uint32_t)((rb_base & 7) << 4);

    float acc[16][4];
#pragma unroll
    for (int i = 0; i < 16; i++)
#pragma unroll
        for (int j = 0; j < 4; j++) acc[i][j] = 0.f;

    int nchunks = K >> 7;
    for (int c = 0; c < nchunks; c++) {
        const __nv_bfloat16* Ah = c ? gHi : aHi;
        const __nv_bfloat16* Al = c ? gLo : aLo;
        for (int ks = 0; ks < 2; ks++) {         // two 64-wide k slices per chunk
            // ---- stage tiles (each: 128 rows x 64 bf16 = 1024 x 16B chunks) ----
            for (int idx = tid; idx < 1024; idx += 256) {
                int r  = idx >> 3;
                int ch = idx & 7;
                uint32_t dst = (uint32_t)r * 128 + (uint32_t)((ch * 16) ^ ((r & 7) << 4));
                size_t ap = (size_t)(rowBase + r) * 128 + ks * 64 + ch * 8;
                *(uint4*)(smem + SM_AH + dst) = *(const uint4*)(Ah + ap);
                *(uint4*)(smem + SM_AL + dst) = *(const uint4*)(Al + ap);
                size_t wp = (size_t)r * K + c * 128 + ks * 64 + ch * 8;
                *(uint4*)(smem + SM_WH + dst) = *(const uint4*)(wtHi + wp);
                *(uint4*)(smem + SM_WL + dst) = *(const uint4*)(wtLo + wp);
            }
            __syncthreads();
            // ---- compute: 4 k-atoms of 16 ----
#pragma unroll
            for (int ka = 0; ka < 4; ka++) {
                uint32_t fAh[2][4], fAl[2][4];
#pragma unroll
                for (int ma = 0; ma < 2; ma++) {
                    uint32_t off = (uint32_t)(ra_base + ma * 16) * 128 +
                                   (((uint32_t)(ka * 32) + kxA) ^ xorA);
                    ldsm4(fAh[ma], sb + SM_AH + off);
                    ldsm4(fAl[ma], sb + SM_AL + off);
                }
#pragma unroll
                for (int nb = 0; nb < 4; nb++) {
                    uint32_t off = (uint32_t)(rb_base + nb * 16) * 128 +
                                   (((uint32_t)(ka * 32) + kxB) ^ xorB);
                    uint32_t wh[4], wl[4];
                    ldsm4(wh, sb + SM_WH + off);
                    ldsm4(wl, sb + SM_WL + off);
#pragma unroll
                    for (int ma = 0; ma < 2; ma++) {
                        float* a0 = acc[ma * 8 + nb * 2];
                        float* a1 = acc[ma * 8 + nb * 2 + 1];
                        mma16816(a0, fAh[ma], wh);
                        mma16816(a1, fAh[ma], wh + 2);
                        mma16816(a0, fAl[ma], wh);
                        mma16816(a1, fAl[ma], wh + 2);
                        mma16816(a0, fAh[ma], wl);
                        mma16816(a1, fAh[ma], wl + 2);
                    }
                }
            }
            __syncthreads();
        }
    }

    // ---- epilogue ----
    int gid = l >> 2, tig = l & 3;
#pragma unroll
    for (int ma = 0; ma < 2; ma++) {
        int r0 = rowBase + m0 + ma * 16 + gid;
        int r1 = r0 + 8;
        float cm0 = crow ? crow[r0] : 1.f, rm0 = rrow ? rrow[r0] : 1.f;
        float cm1 = crow ? crow[r1] : 1.f, rm1 = rrow ? rrow[r1] : 1.f;
#pragma unroll
        for (int na = 0; na < 8; na++) {
            int col = n0 + na * 8 + tig * 2;
            float b0 = bias[col], b1 = bias[col + 1];
            float* ac = acc[ma * 8 + na];
            float o00 = (ac[0] + b0 * cm0) * rm0;
            float o01 = (ac[1] + b1 * cm0) * rm0;
            float o10 = (ac[2] + b0 * cm1) * rm1;
            float o11 = (ac[3] + b1 * cm1) * rm1;
            if (relu) {
                o00 = fmaxf(o00, 0.f); o01 = fmaxf(o01, 0.f);
                o10 = fmaxf(o10, 0.f); o11 = fmaxf(o11, 0.f);
            }
            if (outF) {
                *(float2*)&outF[(size_t)r0 * 128 + col] = make_float2(o00, o01);
                *(float2*)&outF[(size_t)r1 * 128 + col] = make_float2(o10, o11);
            }
            if (outHi) {
                __nv_bfloat16 h00 = __float2bfloat16(o00), h01 = __float2bfloat16(o01);
                __nv_bfloat16 h10 = __float2bfloat16(o10), h11 = __float2bfloat16(o11);
                __nv_bfloat162 hp0; hp0.x = h00; hp0.y = h01;
                __nv_bfloat162 hp1; hp1.x = h10; hp1.y = h11;
                __nv_bfloat162 lp0;
                lp0.x = __float2bfloat16(o00 - __bfloat162float(h00));
                lp0.y = __float2bfloat16(o01 - __bfloat162float(h01));
                __nv_bfloat162 lp1;
                lp1.x = __float2bfloat16(o10 - __bfloat162float(h10));
                lp1.y = __float2bfloat16(o11 - __bfloat162float(h11));
                *(__nv_bfloat162*)&outHi[(size_t)r0 * 128 + col] = hp0;
                *(__nv_bfloat162*)&outHi[(size_t)r1 * 128 + col] = hp1;
                *(__nv_bfloat162*)&outLo[(size_t)r0 * 128 + col] = lp0;
                *(__nv_bfloat162*)&outLo[(size_t)r1 * 128 + col] = lp1;
            }
        }
    }
}

// ======================= SIMT GEMM (eval head, 1024 rows) ====================
__global__ void __launch_bounds__(256)
k_gemm(const float* Alo, const float* Ahi,
       const float* __restrict__ W, const float* __restrict__ bias,
       const float* __restrict__ crow, const float* __restrict__ rrow,
       float* C, int K, int relu) {
    __shared__ float As[16][64];
    __shared__ float Ws[16][128];
    int tid = threadIdx.x;
    int rowBase = blockIdx.x * 64;
    int row0 = (tid >> 5) * 8;
    int col0 = (tid & 31) * 4;
    int lr = tid >> 2, lk = (tid & 3) * 4;
    int wr = tid >> 4, wc = (tid & 15) * 8;

    float acc[8][4];
#pragma unroll
    for (int i = 0; i < 8; i++)
#pragma unroll
        for (int j = 0; j < 4; j++) acc[i][j] = 0.f;

    for (int kt = 0; kt < K; kt += 16) {
        const float* src = (kt < 128) ? Alo : Ahi;
        int kk = (kt < 128) ? kt : (kt - 128);
        float4 a4 = *(const float4*)&src[(size_t)(rowBase + lr) * 128 + kk + lk];
        As[lk + 0][lr] = a4.x;
        As[lk + 1][lr] = a4.y;
        As[lk + 2][lr] = a4.z;
        As[lk + 3][lr] = a4.w;
        float4 w0 = *(const float4*)&W[(size_t)(kt + wr) * 128 + wc];
        float4 w1 = *(const float4*)&W[(size_t)(kt + wr) * 128 + wc + 4];
        *(float4*)&Ws[wr][wc]     = w0;
        *(float4*)&Ws[wr][wc + 4] = w1;
        __syncthreads();
#pragma unroll
        for (int k = 0; k < 16; k++) {
            float4 wv = *(const float4*)&Ws[k][col0];
            float4 aA = *(const float4*)&As[k][row0];
            float4 aB = *(const float4*)&As[k][row0 + 4];
            float av[8] = {aA.x, aA.y, aA.z, aA.w, aB.x, aB.y, aB.z, aB.w};
            float wf[4] = {wv.x, wv.y, wv.z, wv.w};
#pragma unroll
            for (int i = 0; i < 8; i++)
#pragma unroll
                for (int j = 0; j < 4; j++)
                    acc[i][j] = fmaf(av[i], wf[j], acc[i][j]);
        }
        __syncthreads();
    }

    float4 bv = *(const float4*)&bias[col0];
#pragma unroll
    for (int i = 0; i < 8; i++) {
        int row = rowBase + row0 + i;
        float cm = crow ? crow[row] : 1.f;
        float rm = rrow ? rrow[row] : 1.f;
        float4 o;
        o.x = (acc[i][0] + bv.x * cm) * rm;
        o.y = (acc[i][1] + bv.y * cm) * rm;
        o.z = (acc[i][2] + bv.z * cm) * rm;
        o.w = (acc[i][3] + bv.w * cm) * rm;
        if (relu) {
            o.x = fmaxf(o.x, 0.f); o.y = fmaxf(o.y, 0.f);
            o.z = fmaxf(o.z, 0.f); o.w = fmaxf(o.w, 0.f);
        }
        *(float4*)&C[(size_t)row * 128 + col0] = o;
    }
}

// ======================= edge logits =========================================
__global__ void k_edge_logits(const float* __restrict__ lg, const int* __restrict__ snd,
                              const int* __restrict__ rcv, float* __restrict__ out) {
    int gw   = (blockIdx.x * blockDim.x + threadIdx.x) >> 5;
    int lane = threadIdx.x & 31;
    if (gw >= EE) return;
    const float4* l4 = (const float4*)lg;
    int s = snd[gw], r = rcv[gw];
    float4 a = l4[(size_t)s * 32 + lane];
    float4 b = l4[(size_t)r * 32 + lane];
    float p = a.x * b.x + a.y * b.y + a.z * b.z + a.w * b.w;
#pragma unroll
    for (int o = 16; o > 0; o >>= 1) p += __shfl_down_sync(0xffffffffu, p, o);
    if (lane == 0) out[gw] = p;
}

// ======================= value head ==========================================
__global__ void k_value_reduce(const float* __restrict__ h, float* __restrict__ v) {
    int g = blockIdx.x, t = threadIdx.x;
    float acc = 0.f;
    for (int j = 1; j < 64; j++)
        acc += h[((size_t)(g * 64 + j)) * 128 + t];
    v[g * 128 + t] = acc * (1.f / 63.f);
}

__global__ void k_tanh_out(const float* __restrict__ v, const float* __restrict__ wout,
                           const float* __restrict__ bout, float* __restrict__ out) {
    int gw   = (blockIdx.x * blockDim.x + threadIdx.x) >> 5;
    int lane = threadIdx.x & 31;
    if (gw >= BB) return;
    const float4* v4 = (const float4*)v;
    const float4* w4 = (const float4*)wout;
    float4 a = v4[gw * 32 + lane];
    float4 w = w4[lane];
    float p = a.x * w.x + a.y * w.y + a.z * w.z + a.w * w.w;
#pragma unroll
    for (int o = 16; o > 0; o >>= 1) p += __shfl_down_sync(0xffffffffu, p, o);
    if (lane == 0) out[gw] = tanhf(p + bout[0]);
}

// ======================= host launcher =======================================
extern "C" void kernel_launch(void* const* d_in, const int* in_sizes, int n_in,
                              void* d_out, int out_size) {
    const int*   nodes = (const int*)d_in[0];
    const int*   snd   = (const int*)d_in[1];
    const int*   rcv   = (const int*)d_in[2];
    const int*   gsnd  = (const int*)d_in[3];
    const int*   grcv  = (const int*)d_in[4];
    const float* embed = (const float*)d_in[6];
    const float* w1    = (const float*)d_in[7];
    const float* b1    = (const float*)d_in[8];
    const float* w2    = (const float*)d_in[9];
    const float* b2    = (const float*)d_in[10];
    const float* w3    = (const float*)d_in[11];
    const float* b3    = (const float*)d_in[12];
    const float* wl    = (const float*)d_in[13];
    const float* bl    = (const float*)d_in[14];
    const float* ew    = (const float*)d_in[15];
    const float* eb    = (const float*)d_in[16];
    const float* wo    = (const float*)d_in[17];
    const float* bo    = (const float*)d_in[18];
    float* out = (float*)d_out;

    float *h, *lg, *v0, *v1, *s1, *r1, *c1, *s2, *r2, *c2;
    __nv_bfloat16 *mHi, *mLo, *gHi, *gLo;
    __nv_bfloat16 *wt1h, *wt1l, *wt2h, *wt2l, *wt3h, *wt3l, *wtlh, *wtll;
    int *csrM, *csrG, *offM, *offG, *curM, *curG, *cInM, *cInG, *cOutM, *cOutG;
    cudaGetSymbolAddress((void**)&h,    d_h);
    cudaGetSymbolAddress((void**)&lg,   d_lg);
    cudaGetSymbolAddress((void**)&v0,   d_v0);
    cudaGetSymbolAddress((void**)&v1,   d_v1);
    cudaGetSymbolAddress((void**)&mHi,  d_mHi);
    cudaGetSymbolAddress((void**)&mLo,  d_mLo);
    cudaGetSymbolAddress((void**)&gHi,  d_gHi);
    cudaGetSymbolAddress((void**)&gLo,  d_gLo);
    cudaGetSymbolAddress((void**)&wt1h, d_wt1h);
    cudaGetSymbolAddress((void**)&wt1l, d_wt1l);
    cudaGetSymbolAddress((void**)&wt2h, d_wt2h);
    cudaGetSymbolAddress((void**)&wt2l, d_wt2l);
    cudaGetSymbolAddress((void**)&wt3h, d_wt3h);
    cudaGetSymbolAddress((void**)&wt3l, d_wt3l);
    cudaGetSymbolAddress((void**)&wtlh, d_wtlh);
    cudaGetSymbolAddress((void**)&wtll, d_wtll);
    cudaGetSymbolAddress((void**)&s1,   d_s1);
    cudaGetSymbolAddress((void**)&r1,   d_r1);
    cudaGetSymbolAddress((void**)&c1,   d_c1);
    cudaGetSymbolAddress((void**)&s2,   d_s2);
    cudaGetSymbolAddress((void**)&r2,   d_r2);
    cudaGetSymbolAddress((void**)&c2,   d_c2);
    cudaGetSymbolAddress((void**)&csrM, d_csrM);
    cudaGetSymbolAddress((void**)&csrG, d_csrG);
    cudaGetSymbolAddress((void**)&offM, d_offM);
    cudaGetSymbolAddress((void**)&offG, d_offG);
    cudaGetSymbolAddress((void**)&curM, d_curM);
    cudaGetSymbolAddress((void**)&curG, d_curG);
    cudaGetSymbolAddress((void**)&cInM, d_cntInM);
    cudaGetSymbolAddress((void**)&cInG, d_cntInG);
    cudaGetSymbolAddress((void**)&cOutM, d_cntOutM);
    cudaGetSymbolAddress((void**)&cOutG, d_cntOutG);

    cudaFuncSetAttribute(k_mma, cudaFuncAttributeMaxDynamicSharedMemorySize, SM_TOTAL);

    // ---- degree / CSR precompute (layer-invariant) ----
    k_zero_counts<<<NN / 256, 256>>>();
    k_hist<<<(EE  + 255) / 256, 256>>>(snd,  rcv,  EE,  cOutM, cInM);
    k_hist<<<(EEG + 255) / 256, 256>>>(gsnd, grcv, EEG, cOutG, cInG);
    k_norms<<<NN / 256, 256>>>();
    k_scan<<<1, 1024>>>(cInM, offM, curM);
    k_scan<<<1, 1024>>>(cInG, offG, curG);
    k_scatter<<<(EE  + 255) / 256, 256>>>(snd,  rcv,  EE,  curM, csrM);
    k_scatter<<<(EEG + 255) / 256, 256>>>(gsnd, grcv, EEG, curG, csrG);
    k_csum<<<NN / 256, 256>>>(offM, csrM, s1, c1);
    k_csum<<<NN / 256, 256>>>(offG, csrG, s2, c2);

    // ---- weight conversion ----
    for (int i = 0; i < 7; i++) {
        k_wt<<<(128 * 128 + 255) / 256, 256>>>(w1 + (size_t)i * 16384, wt1h + (size_t)i * 16384,
                                               wt1l + (size_t)i * 16384, 128);
        k_wt<<<(128 * 128 + 255) / 256, 256>>>(w2 + (size_t)i * 16384, wt2h + (size_t)i * 16384,
                                               wt2l + (size_t)i * 16384, 128);
        k_wt<<<(256 * 128 + 255) / 256, 256>>>(w3 + (size_t)i * 32768, wt3h + (size_t)i * 32768,
                                               wt3l + (size_t)i * 32768, 256);
    }
    k_wt<<<(128 * 128 + 255) / 256, 256>>>(wl, wtlh, wtll, 128);

    // ---- embed ----
    k_embed<<<(NN * 32 + 255) / 256, 256>>>(nodes, embed, h);

    // ---- 7 GNN layers ----
    for (int i = 0; i < 7; i++) {
        k_aggP<<<NN * 32 / 256, 256>>>(h, offM, csrM, s1, mHi, mLo);
        k_aggP<<<NN * 32 / 256, 256>>>(h, offG, csrG, s2, gHi, gLo);
        // a = r1 * (aggM @ W1 + b1 * c1), written in-place as bf16 pair
        k_mma<<<NN / 128, 256, SM_TOTAL>>>(mHi, mLo, nullptr, nullptr,
                                           wt1h + (size_t)i * 16384, wt1l + (size_t)i * 16384,
                                           128, b1 + i * 128, c1, r1, 0,
                                           nullptr, mHi, mLo);
        // g = r2 * (aggG @ W2 + b2 * c2)
        k_mma<<<NN / 128, 256, SM_TOTAL>>>(gHi, gLo, nullptr, nullptr,
                                           wt2h + (size_t)i * 16384, wt2l + (size_t)i * 16384,
                                           128, b2 + i * 128, c2, r2, 0,
                                           nullptr, gHi, gLo);
        // h = relu([a|g] @ W3 + b3); last layer also emits bf16 pair for logit GEMM
        int last = (i == 6);
        k_mma<<<NN / 128, 256, SM_TOTAL>>>(mHi, mLo, gHi, gLo,
                                           wt3h + (size_t)i * 32768, wt3l + (size_t)i * 32768,
                                           256, b3 + i * 128, nullptr, nullptr, 1,
                                           h, last ? mHi : nullptr, last ? mLo : nullptr);
    }

    // ---- policy head ----
    k_mma<<<NN / 128, 256, SM_TOTAL>>>(mHi, mLo, nullptr, nullptr, wtlh, wtll,
                                       128, bl, nullptr, nullptr, 0,
                                       lg, nullptr, nullptr);
    k_edge_logits<<<(EE * 32) / 256, 256>>>(lg, snd, rcv, out);

    // ---- value head ----
    k_value_reduce<<<BB, 128>>>(h, v0);
    const float* vin = v0;
    float* vout = v1;
    for (int i = 0; i < 5; i++) {
        k_gemm<<<BB / 64, 256>>>(vin, nullptr, ew + (size_t)i * 128 * 128,
                                 eb + i * 128, nullptr, nullptr, vout, 128, 1);
        const float* t = vin; vin = vout; vout = (float*)t;
    }
    k_tanh_out<<<BB * 32 / 256, 256>>>(vin, wo, bo, out + EE);
}

// round 5
// speedup vs baseline: 1.5751x; 1.2665x over previous
#include <cuda_runtime.h>
#include <cuda_bf16.h>
#include <math.h>
#include <stdint.h>

#define NN   65536
#define BB   1024
#define EE   2097152
#define EEG  524288
#define DIM  128

// ======================= portable PTX helpers ================================
__device__ __forceinline__ uint32_t smem_to_u32(const void* p) {
    uint32_t a;
    asm("{ .reg .u64 t; cvta.to.shared.u64 t, %1; cvt.u32.u64 %0, t; }" : "=r"(a) : "l"(p));
    return a;
}

__device__ __forceinline__ void ldsm4(uint32_t* r, uint32_t addr) {
    asm volatile("ldmatrix.sync.aligned.m8n8.x4.shared.b16 {%0,%1,%2,%3}, [%4];"
                 : "=r"(r[0]), "=r"(r[1]), "=r"(r[2]), "=r"(r[3]) : "r"(addr));
}

__device__ __forceinline__ void mma16816(float* c, const uint32_t* a, const uint32_t* b) {
    asm volatile("mma.sync.aligned.m16n8k16.row.col.f32.bf16.bf16.f32 "
                 "{%0,%1,%2,%3}, {%4,%5,%6,%7}, {%8,%9}, {%0,%1,%2,%3};"
                 : "+f"(c[0]), "+f"(c[1]), "+f"(c[2]), "+f"(c[3])
                 : "r"(a[0]), "r"(a[1]), "r"(a[2]), "r"(a[3]), "r"(b[0]), "r"(b[1]));
}

__device__ __forceinline__ void cp_async16(uint32_t dst, const void* src) {
    asm volatile("cp.async.cg.shared.global [%0], [%1], 16;" :: "r"(dst), "l"(src) : "memory");
}

// ======================= static scratch ======================================
__device__ float d_h   [(size_t)NN * DIM];   // node features (fp32)
__device__ float d_lg  [(size_t)NN * DIM];   // logit-head features (fp32)
__device__ float d_v0[BB * DIM];
__device__ float d_v1[BB * DIM];

__device__ __nv_bfloat16 d_mHi[(size_t)NN * DIM], d_mLo[(size_t)NN * DIM];
__device__ __nv_bfloat16 d_gHi[(size_t)NN * DIM], d_gLo[(size_t)NN * DIM];

// converted transposed weights (bf16 hi/lo), layout [n][K]
__device__ __nv_bfloat16 d_wt1h[7*128*128], d_wt1l[7*128*128];
__device__ __nv_bfloat16 d_wt2h[7*128*128], d_wt2l[7*128*128];
__device__ __nv_bfloat16 d_wt3h[7*128*256], d_wt3l[7*128*256];
__device__ __nv_bfloat16 d_wtlh[128*128],   d_wtll[128*128];

__device__ int d_csrM[EE];
__device__ int d_csrG[EEG];
__device__ int d_offM[NN + 1];
__device__ int d_offG[NN + 1];
__device__ int d_curM[NN];
__device__ int d_curG[NN];
__device__ int d_cntOutM[NN], d_cntInM[NN], d_cntOutG[NN], d_cntInG[NN];
__device__ float d_s1[NN], d_r1[NN], d_c1[NN];
__device__ float d_s2[NN], d_r2[NN], d_c2[NN];

// ======================= precompute (fused) ==================================
__global__ void k_zero_counts() {
    int i = blockIdx.x * blockDim.x + threadIdx.x;
    if (i < NN) { d_cntOutM[i] = 0; d_cntInM[i] = 0; d_cntOutG[i] = 0; d_cntInG[i] = 0; }
}

// one launch for both edge sets
__global__ void k_histB(const int* __restrict__ snd, const int* __restrict__ rcv,
                        const int* __restrict__ gsnd, const int* __restrict__ grcv) {
    int e = blockIdx.x * blockDim.x + threadIdx.x;
    if (e < EE) {
        atomicAdd(&d_cntOutM[snd[e]], 1); atomicAdd(&d_cntInM[rcv[e]], 1);
    } else if (e < EE + EEG) {
        int g = e - EE;
        atomicAdd(&d_cntOutG[gsnd[g]], 1); atomicAdd(&d_cntInG[grcv[g]], 1);
    }
}

// norms + init c = s (self-edge term); scatter adds the rest
__global__ void k_normsC() {
    int i = blockIdx.x * blockDim.x + threadIdx.x;
    if (i < NN) {
        float s1 = rsqrtf((float)(d_cntOutM[i] + 1));
        float s2 = rsqrtf((float)(d_cntOutG[i] + 1));
        d_s1[i] = s1; d_c1[i] = s1;
        d_s2[i] = s2; d_c2[i] = s2;
        d_r1[i] = rsqrtf((float)(d_cntInM[i]  + 1));
        d_r2[i] = rsqrtf((float)(d_cntInG[i]  + 1));
    }
}

// two blocks: 0 = move, 1 = grid
__global__ void k_scanB() {
    const int* cnt = blockIdx.x ? d_cntInG : d_cntInM;
    int* off = blockIdx.x ? d_offG : d_offM;
    int* cur = blockIdx.x ? d_curG : d_curM;
    __shared__ int ps[1024];
    int t = threadIdx.x;
    int base = t * 64;
    int s = 0;
    for (int j = 0; j < 64; j++) s += cnt[base + j];
    ps[t] = s;
    __syncthreads();
    for (int d = 1; d < 1024; d <<= 1) {
        int v = 0;
        if (t >= d) v = ps[t - d];
        __syncthreads();
        ps[t] += v;
        __syncthreads();
    }
    int run = (t == 0) ? 0 : ps[t - 1];
    for (int j = 0; j < 64; j++) {
        off[base + j] = run;
        cur[base + j] = run;
        run += cnt[base + j];
    }
    if (t == 1023) off[NN] = run;
}

// scatter both edge sets + fold in csum (c[r] += s[snd]) via float atomics
__global__ void k_scatB(const int* __restrict__ snd, const int* __restrict__ rcv,
                        const int* __restrict__ gsnd, const int* __restrict__ grcv) {
    int e = blockIdx.x * blockDim.x + threadIdx.x;
    if (e < EE) {
        int s = snd[e], r = rcv[e];
        int p = atomicAdd(&d_curM[r], 1);
        d_csrM[p] = s;
        atomicAdd(&d_c1[r], d_s1[s]);
    } else if (e < EE + EEG) {
        int g = e - EE;
        int s = gsnd[g], r = grcv[g];
        int p = atomicAdd(&d_curG[r], 1);
        d_csrG[p] = s;
        atomicAdd(&d_c2[r], d_s2[s]);
    }
}

// ======================= weight convert (all matrices, one launch) ===========
#define WT_S1 (7*16384)
#define WT_S3 (7*32768)
__global__ void k_wt_all(const float* __restrict__ w1, const float* __restrict__ w2,
                         const float* __restrict__ w3, const float* __restrict__ wl) {
    int id = blockIdx.x * blockDim.x + threadIdx.x;
    float v;
    __nv_bfloat16 *hi, *lo;
    int oidx;
    if (id < WT_S1) {
        int layer = id >> 14, w = id & 16383;
        int n = w >> 7, k = w & 127;
        v = w1[(size_t)(layer << 14) + k * 128 + n];
        hi = d_wt1h; lo = d_wt1l; oidx = (layer << 14) + n * 128 + k;
    } else if (id < 2 * WT_S1) {
        int id2 = id - WT_S1;
        int layer = id2 >> 14, w = id2 & 16383;
        int n = w >> 7, k = w & 127;
        v = w2[(size_t)(layer << 14) + k * 128 + n];
        hi = d_wt2h; lo = d_wt2l; oidx = (layer << 14) + n * 128 + k;
    } else if (id < 2 * WT_S1 + WT_S3) {
        int id3 = id - 2 * WT_S1;
        int layer = id3 >> 15, w = id3 & 32767;
        int n = w >> 8, k = w & 255;
        v = w3[(size_t)(layer << 15) + k * 128 + n];
        hi = d_wt3h; lo = d_wt3l; oidx = (layer << 15) + n * 256 + k;
    } else if (id < 2 * WT_S1 + WT_S3 + 16384) {
        int id4 = id - (2 * WT_S1 + WT_S3);
        int n = id4 >> 7, k = id4 & 127;
        v = wl[k * 128 + n];
        hi = d_wtlh; lo = d_wtll; oidx = n * 128 + k;
    } else return;
    __nv_bfloat16 h = __float2bfloat16(v);
    hi[oidx] = h;
    lo[oidx] = __float2bfloat16(v - __bfloat162float(h));
}

// ======================= embedding ==========================================
__global__ void k_embed(const int* __restrict__ nodes, const float* __restrict__ embed,
                        float* __restrict__ h) {
    int i = blockIdx.x * blockDim.x + threadIdx.x;
    if (i < NN * 32) {
        int node = i >> 5;
        int c    = i & 31;
        ((float4*)h)[i] = ((const float4*)embed)[nodes[node] * 32 + c];
    }
}

// ======================= pull aggregation (both edge sets, one launch) =======
__global__ void k_aggB(const float* __restrict__ h) {
    int gw   = (blockIdx.x * blockDim.x + threadIdx.x) >> 5;  // 0 .. 2*NN-1
    int lane = threadIdx.x & 31;
    int isG  = gw >= NN;
    int node = gw - (isG ? NN : 0);
    if (gw >= 2 * NN) return;
    const int* off = isG ? d_offG : d_offM;
    const int* csr = isG ? d_csrG : d_csrM;
    const float* sn = isG ? d_s2 : d_s1;
    __nv_bfloat16* oHi = isG ? d_gHi : d_mHi;
    __nv_bfloat16* oLo = isG ? d_gLo : d_mLo;

    const float4* h4 = (const float4*)h;
    float s0 = sn[node];
    float4 a = h4[(size_t)node * 32 + lane];
    float4 acc;
    acc.x = a.x * s0; acc.y = a.y * s0; acc.z = a.z * s0; acc.w = a.w * s0;
    int e1 = off[node + 1];
    for (int e = off[node]; e < e1; e++) {
        int   s  = csr[e];
        float sc = sn[s];
        float4 v = h4[(size_t)s * 32 + lane];
        acc.x = fmaf(v.x, sc, acc.x);
        acc.y = fmaf(v.y, sc, acc.y);
        acc.z = fmaf(v.z, sc, acc.z);
        acc.w = fmaf(v.w, sc, acc.w);
    }
    __nv_bfloat16 hv[4], lv[4];
    float av[4] = {acc.x, acc.y, acc.z, acc.w};
#pragma unroll
    for (int j = 0; j < 4; j++) {
        hv[j] = __float2bfloat16(av[j]);
        lv[j] = __float2bfloat16(av[j] - __bfloat162float(hv[j]));
    }
    size_t p = (size_t)node * 128 + lane * 4;
    *(uint2*)&oHi[p] = *(uint2*)hv;
    *(uint2*)&oLo[p] = *(uint2*)lv;
}

// ======================= HMMA GEMM (cp.async double-buffered) ================
// C[row, 0:128] = rrow * ( sum_chunks A_chunk @ Wt_chunk^T + bias * crow ), opt relu
// 64-wide k slices; each slice stages 4 tiles (Ah/Al/Wh/Wl), 16KB each.
// Buffer = 64KB, double buffered -> 128KB dynamic smem.
#define SLICE_BYTES 65536
#define SM_TOTAL    131072

__device__ __forceinline__ void stage_slice(
    uint32_t sbuf,                                    // absolute smem addr of buffer
    const __nv_bfloat16* Ah, const __nv_bfloat16* Al,
    const __nv_bfloat16* wtHi, const __nv_bfloat16* wtLo,
    int rowBase, int K, int c, int ks, int tid) {
#pragma unroll
    for (int j = 0; j < 16; j++) {
        int tile = j >> 2;
        int cidx = tid + (j & 3) * 256;    // 0..1023 within tile
        int r = cidx >> 3, ch = cidx & 7;
        uint32_t dst = sbuf + tile * 16384 + (uint32_t)r * 128 +
                       (uint32_t)((ch * 16) ^ ((r & 7) << 4));
        const __nv_bfloat16* src;
        if (tile == 0)      src = Ah   + (size_t)(rowBase + r) * 128 + ks * 64 + ch * 8;
        else if (tile == 1) src = Al   + (size_t)(rowBase + r) * 128 + ks * 64 + ch * 8;
        else if (tile == 2) src = wtHi + (size_t)r * K + c * 128 + ks * 64 + ch * 8;
        else                src = wtLo + (size_t)r * K + c * 128 + ks * 64 + ch * 8;
        cp_async16(dst, src);
    }
    asm volatile("cp.async.commit_group;" ::: "memory");
}

__device__ __forceinline__ void mma_compute_slice(
    uint32_t base, int ra_base, uint32_t kxA, uint32_t xorA,
    int rb_base, uint32_t kxB, uint32_t xorB, float acc[16][4]) {
#pragma unroll
    for (int ka = 0; ka < 4; ka++) {
        uint32_t fAh[2][4], fAl[2][4];
#pragma unroll
        for (int ma = 0; ma < 2; ma++) {
            uint32_t off = (uint32_t)(ra_base + ma * 16) * 128 +
                           (((uint32_t)(ka * 32) + kxA) ^ xorA);
            ldsm4(fAh[ma], base + off);
            ldsm4(fAl[ma], base + 16384 + off);
        }
#pragma unroll
        for (int nb = 0; nb < 4; nb++) {
            uint32_t off = (uint32_t)(rb_base + nb * 16) * 128 +
                           (((uint32_t)(ka * 32) + kxB) ^ xorB);
            uint32_t wh[4], wl[4];
            ldsm4(wh, base + 32768 + off);
            ldsm4(wl, base + 49152 + off);
#pragma unroll
            for (int ma = 0; ma < 2; ma++) {
                float* a0 = acc[ma * 8 + nb * 2];
                float* a1 = acc[ma * 8 + nb * 2 + 1];
                mma16816(a0, fAh[ma], wh);
                mma16816(a1, fAh[ma], wh + 2);
                mma16816(a0, fAl[ma], wh);
                mma16816(a1, fAl[ma], wh + 2);
                mma16816(a0, fAh[ma], wl);
                mma16816(a1, fAh[ma], wl + 2);
            }
        }
    }
}

__device__ __forceinline__ void mma_body(
    const __nv_bfloat16* aHi, const __nv_bfloat16* aLo,
    const __nv_bfloat16* gHi, const __nv_bfloat16* gLo,
    const __nv_bfloat16* wtHi, const __nv_bfloat16* wtLo,
    int K, const float* bias, const float* crow, const float* rrow,
    int relu, float* outF, __nv_bfloat16* outHi, __nv_bfloat16* outLo,
    int rowBase, char* smem) {
    uint32_t sb = smem_to_u32(smem);
    int tid = threadIdx.x;
    int wid = tid >> 5;
    int l   = tid & 31;
    int m0 = (wid >> 1) * 32;
    int n0 = (wid & 1) * 64;

    int ra_base = m0 + (l & 7) + ((l >> 3) & 1) * 8;
    uint32_t kxA = ((l >> 4) & 1) * 16;
    uint32_t xorA = (uint32_t)((ra_base & 7) << 4);
    int rb_base = n0 + (l & 7) + ((l >> 4) & 1) * 8;
    uint32_t kxB = ((l >> 3) & 1) * 16;
    uint32_t xorB = (uint32_t)((rb_base & 7) << 4);

    float acc[16][4];
#pragma unroll
    for (int i = 0; i < 16; i++)
#pragma unroll
        for (int j = 0; j < 4; j++) acc[i][j] = 0.f;

    int nslices = K >> 6;
    // prologue: slice 0 (chunk 0, ks 0)
    stage_slice(sb, aHi, aLo, wtHi, wtLo, rowBase, K, 0, 0, tid);
    for (int s = 0; s < nslices; s++) {
        if (s + 1 < nslices) {
            int c = (s + 1) >> 1, ks = (s + 1) & 1;
            stage_slice(sb + ((s + 1) & 1) * SLICE_BYTES,
                        c ? gHi : aHi, c ? gLo : aLo, wtHi, wtLo,
                        rowBase, K, c, ks, tid);
            asm volatile("cp.async.wait_group 1;" ::: "memory");
        } else {
            asm volatile("cp.async.wait_group 0;" ::: "memory");
        }
        __syncthreads();
        mma_compute_slice(sb + (s & 1) * SLICE_BYTES,
                          ra_base, kxA, xorA, rb_base, kxB, xorB, acc);
        __syncthreads();
    }

    // epilogue
    int gid = l >> 2, tig = l & 3;
#pragma unroll
    for (int ma = 0; ma < 2; ma++) {
        int r0 = rowBase + m0 + ma * 16 + gid;
        int r1 = r0 + 8;
        float cm0 = crow ? crow[r0] : 1.f, rm0 = rrow ? rrow[r0] : 1.f;
        float cm1 = crow ? crow[r1] : 1.f, rm1 = rrow ? rrow[r1] : 1.f;
#pragma unroll
        for (int na = 0; na < 8; na++) {
            int col = n0 + na * 8 + tig * 2;
            float b0 = bias[col], b1 = bias[col + 1];
            float* ac = acc[ma * 8 + na];
            float o00 = (ac[0] + b0 * cm0) * rm0;
            float o01 = (ac[1] + b1 * cm0) * rm0;
            float o10 = (ac[2] + b0 * cm1) * rm1;
            float o11 = (ac[3] + b1 * cm1) * rm1;
            if (relu) {
                o00 = fmaxf(o00, 0.f); o01 = fmaxf(o01, 0.f);
                o10 = fmaxf(o10, 0.f); o11 = fmaxf(o11, 0.f);
            }
            if (outF) {
                *(float2*)&outF[(size_t)r0 * 128 + col] = make_float2(o00, o01);
                *(float2*)&outF[(size_t)r1 * 128 + col] = make_float2(o10, o11);
            }
            if (outHi) {
                __nv_bfloat16 h00 = __float2bfloat16(o00), h01 = __float2bfloat16(o01);
                __nv_bfloat16 h10 = __float2bfloat16(o10), h11 = __float2bfloat16(o11);
                __nv_bfloat162 hp0; hp0.x = h00; hp0.y = h01;
                __nv_bfloat162 hp1; hp1.x = h10; hp1.y = h11;
                __nv_bfloat162 lp0;
                lp0.x = __float2bfloat16(o00 - __bfloat162float(h00));
                lp0.y = __float2bfloat16(o01 - __bfloat162float(h01));
                __nv_bfloat162 lp1;
                lp1.x = __float2bfloat16(o10 - __bfloat162float(h10));
                lp1.y = __float2bfloat16(o11 - __bfloat162float(h11));
                *(__nv_bfloat162*)&outHi[(size_t)r0 * 128 + col] = hp0;
                *(__nv_bfloat162*)&outHi[(size_t)r1 * 128 + col] = hp1;
                *(__nv_bfloat162*)&outLo[(size_t)r0 * 128 + col] = lp0;
                *(__nv_bfloat162*)&outLo[(size_t)r1 * 128 + col] = lp1;
            }
        }
    }
}

__global__ void __launch_bounds__(256)
k_mmaS(const __nv_bfloat16* aHi, const __nv_bfloat16* aLo,
       const __nv_bfloat16* gHi, const __nv_bfloat16* gLo,
       const __nv_bfloat16* wtHi, const __nv_bfloat16* wtLo,
       int K, const float* bias, const float* crow, const float* rrow,
       int relu, float* outF, __nv_bfloat16* outHi, __nv_bfloat16* outLo) {
    extern __shared__ __align__(16) char smem[];
    mma_body(aHi, aLo, gHi, gLo, wtHi, wtLo, K, bias, crow, rrow,
             relu, outF, outHi, outLo, blockIdx.x * 128, smem);
}

// paired W1/W2 GEMMs: blocks [0,512) = set 1 (move), [512,1024) = set 2 (grid)
__global__ void __launch_bounds__(256)
k_mmaD(const __nv_bfloat16* a1Hi, const __nv_bfloat16* a1Lo,
       const __nv_bfloat16* wt1Hi, const __nv_bfloat16* wt1Lo,
       const float* bias1, const float* crow1, const float* rrow1,
       __nv_bfloat16* out1Hi, __nv_bfloat16* out1Lo,
       const __nv_bfloat16* a2Hi, const __nv_bfloat16* a2Lo,
       const __nv_bfloat16* wt2Hi, const __nv_bfloat16* wt2Lo,
       const float* bias2, const float* crow2, const float* rrow2,
       __nv_bfloat16* out2Hi, __nv_bfloat16* out2Lo) {
    extern __shared__ __align__(16) char smem[];
    if (blockIdx.x < 512)
        mma_body(a1Hi, a1Lo, nullptr, nullptr, wt1Hi, wt1Lo, 128,
                 bias1, crow1, rrow1, 0, nullptr, out1Hi, out1Lo,
                 blockIdx.x * 128, smem);
    else
        mma_body(a2Hi, a2Lo, nullptr, nullptr, wt2Hi, wt2Lo, 128,
                 bias2, crow2, rrow2, 0, nullptr, out2Hi, out2Lo,
                 (blockIdx.x - 512) * 128, smem);
}

// ======================= SIMT GEMM (eval head, 1024 rows) ====================
__global__ void __launch_bounds__(256)
k_gemm(const float* Alo, const float* Ahi,
       const float* __restrict__ W, const float* __restrict__ bias,
       const float* __restrict__ crow, const float* __restrict__ rrow,
       float* C, int K, int relu) {
    __shared__ float As[16][64];
    __shared__ float Ws[16][128];
    int tid = threadIdx.x;
    int rowBase = blockIdx.x * 64;
    int row0 = (tid >> 5) * 8;
    int col0 = (tid & 31) * 4;
    int lr = tid >> 2, lk = (tid & 3) * 4;
    int wr = tid >> 4, wc = (tid & 15) * 8;

    float acc[8][4];
#pragma unroll
    for (int i = 0; i < 8; i++)
#pragma unroll
        for (int j = 0; j < 4; j++) acc[i][j] = 0.f;

    for (int kt = 0; kt < K; kt += 16) {
        const float* src = (kt < 128) ? Alo : Ahi;
        int kk = (kt < 128) ? kt : (kt - 128);
        float4 a4 = *(const float4*)&src[(size_t)(rowBase + lr) * 128 + kk + lk];
        As[lk + 0][lr] = a4.x;
        As[lk + 1][lr] = a4.y;
        As[lk + 2][lr] = a4.z;
        As[lk + 3][lr] = a4.w;
        float4 w0 = *(const float4*)&W[(size_t)(kt + wr) * 128 + wc];
        float4 w1 = *(const float4*)&W[(size_t)(kt + wr) * 128 + wc + 4];
        *(float4*)&Ws[wr][wc]     = w0;
        *(float4*)&Ws[wr][wc + 4] = w1;
        __syncthreads();
#pragma unroll
        for (int k = 0; k < 16; k++) {
            float4 wv = *(const float4*)&Ws[k][col0];
            float4 aA = *(const float4*)&As[k][row0];
            float4 aB = *(const float4*)&As[k][row0 + 4];
            float av[8] = {aA.x, aA.y, aA.z, aA.w, aB.x, aB.y, aB.z, aB.w};
            float wf[4] = {wv.x, wv.y, wv.z, wv.w};
#pragma unroll
            for (int i = 0; i < 8; i++)
#pragma unroll
                for (int j = 0; j < 4; j++)
                    acc[i][j] = fmaf(av[i], wf[j], acc[i][j]);
        }
        __syncthreads();
    }

    float4 bv = *(const float4*)&bias[col0];
#pragma unroll
    for (int i = 0; i < 8; i++) {
        int row = rowBase + row0 + i;
        float cm = crow ? crow[row] : 1.f;
        float rm = rrow ? rrow[row] : 1.f;
        float4 o;
        o.x = (acc[i][0] + bv.x * cm) * rm;
        o.y = (acc[i][1] + bv.y * cm) * rm;
        o.z = (acc[i][2] + bv.z * cm) * rm;
        o.w = (acc[i][3] + bv.w * cm) * rm;
        if (relu) {
            o.x = fmaxf(o.x, 0.f); o.y = fmaxf(o.y, 0.f);
            o.z = fmaxf(o.z, 0.f); o.w = fmaxf(o.w, 0.f);
        }
        *(float4*)&C[(size_t)row * 128 + col0] = o;
    }
}

// ======================= edge logits =========================================
__global__ void k_edge_logits(const float* __restrict__ lg, const int* __restrict__ snd,
                              const int* __restrict__ rcv, float* __restrict__ out) {
    int gw   = (blockIdx.x * blockDim.x + threadIdx.x) >> 5;
    int lane = threadIdx.x & 31;
    if (gw >= EE) return;
    const float4* l4 = (const float4*)lg;
    int s = snd[gw], r = rcv[gw];
    float4 a = l4[(size_t)s * 32 + lane];
    float4 b = l4[(size_t)r * 32 + lane];
    float p = a.x * b.x + a.y * b.y + a.z * b.z + a.w * b.w;
#pragma unroll
    for (int o = 16; o > 0; o >>= 1) p += __shfl_down_sync(0xffffffffu, p, o);
    if (lane == 0) out[gw] = p;
}

// ======================= value head ==========================================
__global__ void k_value_reduce(const float* __restrict__ h, float* __restrict__ v) {
    int g = blockIdx.x, t = threadIdx.x;
    float acc = 0.f;
    for (int j = 1; j < 64; j++)
        acc += h[((size_t)(g * 64 + j)) * 128 + t];
    v[g * 128 + t] = acc * (1.f / 63.f);
}

__global__ void k_tanh_out(const float* __restrict__ v, const float* __restrict__ wout,
                           const float* __restrict__ bout, float* __restrict__ out) {
    int gw   = (blockIdx.x * blockDim.x + threadIdx.x) >> 5;
    int lane = threadIdx.x & 31;
    if (gw >= BB) return;
    const float4* v4 = (const float4*)v;
    const float4* w4 = (const float4*)wout;
    float4 a = v4[gw * 32 + lane];
    float4 w = w4[lane];
    float p = a.x * w.x + a.y * w.y + a.z * w.z + a.w * w.w;
#pragma unroll
    for (int o = 16; o > 0; o >>= 1) p += __shfl_down_sync(0xffffffffu, p, o);
    if (lane == 0) out[gw] = tanhf(p + bout[0]);
}

// ======================= host launcher =======================================
extern "C" void kernel_launch(void* const* d_in, const int* in_sizes, int n_in,
                              void* d_out, int out_size) {
    const int*   nodes = (const int*)d_in[0];
    const int*   snd   = (const int*)d_in[1];
    const int*   rcv   = (const int*)d_in[2];
    const int*   gsnd  = (const int*)d_in[3];
    const int*   grcv  = (const int*)d_in[4];
    const float* embed = (const float*)d_in[6];
    const float* w1    = (const float*)d_in[7];
    const float* b1    = (const float*)d_in[8];
    const float* w2    = (const float*)d_in[9];
    const float* b2    = (const float*)d_in[10];
    const float* w3    = (const float*)d_in[11];
    const float* b3    = (const float*)d_in[12];
    const float* wl    = (const float*)d_in[13];
    const float* bl    = (const float*)d_in[14];
    const float* ew    = (const float*)d_in[15];
    const float* eb    = (const float*)d_in[16];
    const float* wo    = (const float*)d_in[17];
    const float* bo    = (const float*)d_in[18];
    float* out = (float*)d_out;

    float *h, *lg, *v0, *v1, *s1, *r1, *c1, *s2, *r2, *c2;
    __nv_bfloat16 *mHi, *mLo, *gHi, *gLo;
    __nv_bfloat16 *wt1h, *wt1l, *wt2h, *wt2l, *wt3h, *wt3l, *wtlh, *wtll;
    cudaGetSymbolAddress((void**)&h,    d_h);
    cudaGetSymbolAddress((void**)&lg,   d_lg);
    cudaGetSymbolAddress((void**)&v0,   d_v0);
    cudaGetSymbolAddress((void**)&v1,   d_v1);
    cudaGetSymbolAddress((void**)&mHi,  d_mHi);
    cudaGetSymbolAddress((void**)&mLo,  d_mLo);
    cudaGetSymbolAddress((void**)&gHi,  d_gHi);
    cudaGetSymbolAddress((void**)&gLo,  d_gLo);
    cudaGetSymbolAddress((void**)&wt1h, d_wt1h);
    cudaGetSymbolAddress((void**)&wt1l, d_wt1l);
    cudaGetSymbolAddress((void**)&wt2h, d_wt2h);
    cudaGetSymbolAddress((void**)&wt2l, d_wt2l);
    cudaGetSymbolAddress((void**)&wt3h, d_wt3h);
    cudaGetSymbolAddress((void**)&wt3l, d_wt3l);
    cudaGetSymbolAddress((void**)&wtlh, d_wtlh);
    cudaGetSymbolAddress((void**)&wtll, d_wtll);
    cudaGetSymbolAddress((void**)&s1,   d_s1);
    cudaGetSymbolAddress((void**)&r1,   d_r1);
    cudaGetSymbolAddress((void**)&c1,   d_c1);
    cudaGetSymbolAddress((void**)&s2,   d_s2);
    cudaGetSymbolAddress((void**)&r2,   d_r2);
    cudaGetSymbolAddress((void**)&c2,   d_c2);

    cudaFuncSetAttribute(k_mmaS, cudaFuncAttributeMaxDynamicSharedMemorySize, SM_TOTAL);
    cudaFuncSetAttribute(k_mmaD, cudaFuncAttributeMaxDynamicSharedMemorySize, SM_TOTAL);

    // ---- weight conversion + embed (independent, front-loaded) ----
    k_wt_all<<<(2 * WT_S1 + WT_S3 + 16384 + 255) / 256, 256>>>(w1, w2, w3, wl);
    k_embed<<<(NN * 32 + 255) / 256, 256>>>(nodes, embed, h);

    // ---- degree / CSR precompute (layer-invariant) ----
    k_zero_counts<<<NN / 256, 256>>>();
    k_histB<<<(EE + EEG + 255) / 256, 256>>>(snd, rcv, gsnd, grcv);
    k_normsC<<<NN / 256, 256>>>();
    k_scanB<<<2, 1024>>>();
    k_scatB<<<(EE + EEG + 255) / 256, 256>>>(snd, rcv, gsnd, grcv);

    // ---- 7 GNN layers ----
    for (int i = 0; i < 7; i++) {
        k_aggB<<<2 * NN * 32 / 256, 256>>>(h);
        // paired: a = r1*(aggM@W1 + b1*c1);  g = r2*(aggG@W2 + b2*c2)
        k_mmaD<<<1024, 256, SM_TOTAL>>>(
            mHi, mLo, wt1h + (size_t)i * 16384, wt1l + (size_t)i * 16384,
            b1 + i * 128, c1, r1, mHi, mLo,
            gHi, gLo, wt2h + (size_t)i * 16384, wt2l + (size_t)i * 16384,
            b2 + i * 128, c2, r2, gHi, gLo);
        // h = relu([a|g] @ W3 + b3); last layer also emits bf16 pair for logit GEMM
        int last = (i == 6);
        k_mmaS<<<512, 256, SM_TOTAL>>>(mHi, mLo, gHi, gLo,
                                       wt3h + (size_t)i * 32768, wt3l + (size_t)i * 32768,
                                       256, b3 + i * 128, nullptr, nullptr, 1,
                                       h, last ? mHi : nullptr, last ? mLo : nullptr);
    }

    // ---- policy head ----
    k_mmaS<<<512, 256, SM_TOTAL>>>(mHi, mLo, nullptr, nullptr, wtlh, wtll,
                                   128, bl, nullptr, nullptr, 0,
                                   lg, nullptr, nullptr);
    k_edge_logits<<<(EE * 32) / 256, 256>>>(lg, snd, rcv, out);

    // ---- value head ----
    k_value_reduce<<<BB, 128>>>(h, v0);
    const float* vin = v0;
    float* vout = v1;
    for (int i = 0; i < 5; i++) {
        k_gemm<<<BB / 64, 256>>>(vin, nullptr, ew + (size_t)i * 128 * 128,
                                 eb + i * 128, nullptr, nullptr, vout, 128, 1);
        const float* t = vin; vin = vout; vout = (float*)t;
    }
    k_tanh_out<<<BB * 32 / 256, 256>>>(vin, wo, bo, out + EE);
}